// round 1
// baseline (speedup 1.0000x reference)
#include <cuda_runtime.h>
#include <math.h>

// ---------------------------------------------------------------------------
// Problem constants
//   gwc_feature    (4, 96,160,288)   concat_feature (4, 12,160,288)
//   downsample: conv3x3 s2 p1 -> BN -> leaky(0.1) -> conv1x1 -> softmax(9)
//               -> weighted unfold sum        (HO=80, WO=144)
//   volume: D=24, gwc groups=8 (cpg=12), out (2, 8+24, 24, 80, 144) f32
// ---------------------------------------------------------------------------

#define HO_ 80
#define WO_ 144
#define HW_ (HO_*WO_)

// scratch (bss, no allocation)
static __device__ float g_y1   [4*192*HW_];  // gwc conv1+bn+leaky
static __device__ float g_mask [4*144*HW_];  // gwc conv2 logits
static __device__ float g_g8x  [4* 96*HW_];  // gwc downsampled
static __device__ float g_cy1  [4* 24*HW_];
static __device__ float g_cmask[4*108*HW_];
static __device__ float g_c8x  [4* 12*HW_];

// ---------------------------------------------------------------------------
// Implicit-im2col fp32 GEMM:  out[b][oc][ho][wo] = sum_k W[oc][k] * patch[k][pos]
// Tile: 64(oc) x 64(pos), BK=16, 256 threads, 4x4 microtile.
// KS=3 -> k=(ic,kh,kw); KS=1 -> k=ic. Optional fused BN+leaky epilogue.
// ---------------------------------------------------------------------------
template<int KS, bool DO_BN>
__global__ void conv_gemm_kernel(
    const float* __restrict__ x, const float* __restrict__ w,
    const float* __restrict__ bn_g, const float* __restrict__ bn_b,
    const float* __restrict__ bn_m, const float* __restrict__ bn_v,
    float* __restrict__ out,
    int Cin, int Cout, int Hin, int Win, int Hout, int Wout, int Bsz,
    int stride, int pad)
{
    __shared__ float As[16][68];   // [k][oc]   (+4 pad: bank + float4 align)
    __shared__ float Bs[16][68];   // [k][pos]

    const int K    = Cin * KS * KS;
    const int HW   = Hout * Wout;
    const int Npos = Bsz * HW;

    const int bm = blockIdx.y * 64;
    const int bn = blockIdx.x * 64;
    const int tx = threadIdx.x;          // 0..15 -> pos
    const int ty = threadIdx.y;          // 0..15 -> oc
    const int tid = ty * 16 + tx;

    // B-load: this thread always loads column nn, rows kb, kb+4, kb+8, kb+12
    const int nn = tid & 63;
    const int kb = tid >> 6;
    const int posb = bn + nn;
    int bb = 0, ho = 0, wo = 0;
    const bool posok = posb < Npos;
    if (posok) {
        bb = posb / HW;
        int rp = posb - bb * HW;
        ho = rp / Wout;
        wo = rp - ho * Wout;
    }
    // A-load: column ka=tid&15, rows am, am+16, am+32, am+48
    const int am = tid >> 4;
    const int ak = tid & 15;

    float acc[4][4];
    #pragma unroll
    for (int i = 0; i < 4; i++)
        #pragma unroll
        for (int j = 0; j < 4; j++) acc[i][j] = 0.f;

    for (int k0 = 0; k0 < K; k0 += 16) {
        const int ka = k0 + ak;
        #pragma unroll
        for (int i = 0; i < 4; i++) {
            const int mm = am + i * 16;
            const int oc = bm + mm;
            As[ak][mm] = (oc < Cout && ka < K) ? w[oc * K + ka] : 0.f;
        }
        #pragma unroll
        for (int i = 0; i < 4; i++) {
            const int kk = kb + i * 4;
            const int k  = k0 + kk;
            float v = 0.f;
            if (posok && k < K) {
                int ic, kh, kw2;
                if (KS == 1) { ic = k; kh = 0; kw2 = 0; }
                else { ic = k / 9; int r = k - ic * 9; kh = r / 3; kw2 = r - kh * 3; }
                const int hi = ho * stride + kh - pad;
                const int wi = wo * stride + kw2 - pad;
                if (hi >= 0 && hi < Hin && wi >= 0 && wi < Win)
                    v = __ldg(&x[((size_t)(bb * Cin + ic) * Hin + hi) * Win + wi]);
            }
            Bs[kk][nn] = v;
        }
        __syncthreads();

        #pragma unroll
        for (int kk = 0; kk < 16; kk++) {
            float a0 = As[kk][ty*4+0], a1 = As[kk][ty*4+1],
                  a2 = As[kk][ty*4+2], a3 = As[kk][ty*4+3];
            float c0 = Bs[kk][tx*4+0], c1 = Bs[kk][tx*4+1],
                  c2 = Bs[kk][tx*4+2], c3 = Bs[kk][tx*4+3];
            acc[0][0] += a0*c0; acc[0][1] += a0*c1; acc[0][2] += a0*c2; acc[0][3] += a0*c3;
            acc[1][0] += a1*c0; acc[1][1] += a1*c1; acc[1][2] += a1*c2; acc[1][3] += a1*c3;
            acc[2][0] += a2*c0; acc[2][1] += a2*c1; acc[2][2] += a2*c2; acc[2][3] += a2*c3;
            acc[3][0] += a3*c0; acc[3][1] += a3*c1; acc[3][2] += a3*c2; acc[3][3] += a3*c3;
        }
        __syncthreads();
    }

    #pragma unroll
    for (int i = 0; i < 4; i++) {
        const int oc = bm + ty * 4 + i;
        if (oc >= Cout) continue;
        float scale = 1.f, bias = 0.f;
        if (DO_BN) {
            const float s = bn_g[oc] * rsqrtf(bn_v[oc] + 1e-5f);
            scale = s;
            bias  = bn_b[oc] - bn_m[oc] * s;
        }
        #pragma unroll
        for (int j = 0; j < 4; j++) {
            const int pos = bn + tx * 4 + j;
            if (pos >= Npos) continue;
            float v = acc[i][j];
            if (DO_BN) {
                v = v * scale + bias;
                v = (v >= 0.f) ? v : 0.1f * v;
            }
            const int b2 = pos / HW;
            const int rp = pos - b2 * HW;
            out[((size_t)(b2 * Cout + oc) * HW) + rp] = v;
        }
    }
}

// ---------------------------------------------------------------------------
// Fused: softmax over 9 logits per (b, group, ho, wo), then weighted unfold
// sum over the 3x3 stride-2 patch. Channel for (i, g) is ch = i*G + g.
// ---------------------------------------------------------------------------
__global__ void adaptive_ds_kernel(
    const float* __restrict__ x, const float* __restrict__ logits,
    float* __restrict__ out,
    int Cin, int G, int Hin, int Win, int Bsz)
{
    const int idx = blockIdx.x * blockDim.x + threadIdx.x;
    const int total = Bsz * G * HW_;
    if (idx >= total) return;

    const int wo = idx % WO_;
    int t = idx / WO_;
    const int ho = t % HO_;  t /= HO_;
    const int g  = t % G;
    const int b  = t / G;

    float lg[9];
    float mx = -1e30f;
    const size_t lbase = ((size_t)(b * G * 9 + g * 9) * HW_) + ho * WO_ + wo;
    #pragma unroll
    for (int k = 0; k < 9; k++) {
        lg[k] = logits[lbase + (size_t)k * HW_];
        mx = fmaxf(mx, lg[k]);
    }
    float s = 0.f;
    #pragma unroll
    for (int k = 0; k < 9; k++) { lg[k] = expf(lg[k] - mx); s += lg[k]; }
    const float inv = 1.f / s;
    #pragma unroll
    for (int k = 0; k < 9; k++) lg[k] *= inv;

    const int cpg = Cin / G;
    for (int i = 0; i < cpg; i++) {
        const int ch = i * G + g;
        const float* xb = x + (size_t)(b * Cin + ch) * Hin * Win;
        float acc = 0.f;
        #pragma unroll
        for (int kh = 0; kh < 3; kh++) {
            const int hi = 2 * ho + kh - 1;
            if (hi < 0 || hi >= Hin) continue;
            #pragma unroll
            for (int kw = 0; kw < 3; kw++) {
                const int wi = 2 * wo + kw - 1;
                if (wi < 0 || wi >= Win) continue;
                acc += lg[kh * 3 + kw] * __ldg(&xb[(size_t)hi * Win + wi]);
            }
        }
        out[((size_t)(b * Cin + ch) * HW_) + ho * WO_ + wo] = acc;
    }
}

// ---------------------------------------------------------------------------
// Cost volumes. Output (2, 32, 24, 80, 144):
//   c in [0,8):   gwc corr  mean_{cc<12} l[g*12+cc][w] * r[g*12+cc][w-d]   (w>=d)
//   c in [8,20):  l_c[c-8][w]        if w>=d else 0
//   c in [20,32): r_c[c-20][w-d]     if w>=d else 0
// ---------------------------------------------------------------------------
__global__ void build_volume_kernel(
    const float* __restrict__ g8x, const float* __restrict__ c8x,
    float* __restrict__ out)
{
    const int W = WO_, H = HO_, D = 24, OC = 32;
    const int total = 2 * OC * D * H * W;
    const int idx = blockIdx.x * blockDim.x + threadIdx.x;
    if (idx >= total) return;

    const int w = idx % W;
    int t = idx / W;
    const int h = t % H;  t /= H;
    const int d = t % D;  t /= D;
    const int c = t % OC;
    const int b = t / OC;

    float v = 0.f;
    if (c < 8) {
        if (w >= d) {
            const float* l = g8x + ((size_t)(b       * 96 + c * 12) * H + h) * W;
            const float* r = g8x + ((size_t)((b + 2) * 96 + c * 12) * H + h) * W;
            float acc = 0.f;
            #pragma unroll
            for (int cc = 0; cc < 12; cc++)
                acc += __ldg(&l[(size_t)cc * H * W + w]) * __ldg(&r[(size_t)cc * H * W + w - d]);
            v = acc * (1.f / 12.f);
        }
    } else if (c < 20) {
        const int ch = c - 8;
        if (w >= d) v = __ldg(&c8x[((size_t)(b * 12 + ch) * H + h) * W + w]);
    } else {
        const int ch = c - 20;
        if (w >= d) v = __ldg(&c8x[((size_t)((b + 2) * 12 + ch) * H + h) * W + w - d]);
    }
    out[idx] = v;
}

// ---------------------------------------------------------------------------
extern "C" void kernel_launch(void* const* d_in, const int* in_sizes, int n_in,
                              void* d_out, int out_size)
{
    const float* gwc = (const float*)d_in[0];
    const float* cat = (const float*)d_in[1];
    const float* gw1 = (const float*)d_in[2];
    const float* gbg = (const float*)d_in[3];
    const float* gbb = (const float*)d_in[4];
    const float* gbm = (const float*)d_in[5];
    const float* gbv = (const float*)d_in[6];
    const float* gw2 = (const float*)d_in[7];
    const float* cw1 = (const float*)d_in[8];
    const float* cbg = (const float*)d_in[9];
    const float* cbb = (const float*)d_in[10];
    const float* cbm = (const float*)d_in[11];
    const float* cbv = (const float*)d_in[12];
    const float* cw2 = (const float*)d_in[13];
    float* out = (float*)d_out;

    float *y1, *mask, *g8x, *cy1, *cmask, *c8x;
    cudaGetSymbolAddress((void**)&y1,    g_y1);
    cudaGetSymbolAddress((void**)&mask,  g_mask);
    cudaGetSymbolAddress((void**)&g8x,   g_g8x);
    cudaGetSymbolAddress((void**)&cy1,   g_cy1);
    cudaGetSymbolAddress((void**)&cmask, g_cmask);
    cudaGetSymbolAddress((void**)&c8x,   g_c8x);

    const dim3 thr(16, 16);
    const int nposTiles = (4 * HW_ + 63) / 64;   // 720

    // gwc branch
    conv_gemm_kernel<3, true><<<dim3(nposTiles, 3), thr>>>(
        gwc, gw1, gbg, gbb, gbm, gbv, y1, 96, 192, 160, 288, HO_, WO_, 4, 2, 1);
    conv_gemm_kernel<1, false><<<dim3(nposTiles, 3), thr>>>(
        y1, gw2, nullptr, nullptr, nullptr, nullptr, mask, 192, 144, HO_, WO_, HO_, WO_, 4, 1, 0);
    adaptive_ds_kernel<<<(4 * 16 * HW_ + 255) / 256, 256>>>(
        gwc, mask, g8x, 96, 16, 160, 288, 4);

    // concat branch
    conv_gemm_kernel<3, true><<<dim3(nposTiles, 1), thr>>>(
        cat, cw1, cbg, cbb, cbm, cbv, cy1, 12, 24, 160, 288, HO_, WO_, 4, 2, 1);
    conv_gemm_kernel<1, false><<<dim3(nposTiles, 2), thr>>>(
        cy1, cw2, nullptr, nullptr, nullptr, nullptr, cmask, 24, 108, HO_, WO_, HO_, WO_, 4, 1, 0);
    adaptive_ds_kernel<<<(4 * 12 * HW_ + 255) / 256, 256>>>(
        cat, cmask, c8x, 12, 12, 160, 288, 4);

    // volumes -> d_out
    build_volume_kernel<<<(2 * 32 * 24 * HW_ + 255) / 256, 256>>>(g8x, c8x, out);
}